// round 10
// baseline (speedup 1.0000x reference)
#include <cuda_runtime.h>
#include <math.h>

#define H  96
#define W  96
#define HW (H*W)
#define MAXB 8
#define COLS_PB 16                      // columns per block
#define PX_PT  2                        // adjacent-column pixels per thread
#define BLK_PER_B (W / COLS_PB)         // 6 blocks per batch image
#define NTHR 768                        // 96 rows x 8 col-pairs
// sentinel: real max d^2 = 2*95^2 = 18050 < 23742, and 23742+95^2 = 32767
// fits the 15-bit packed field. best >= SENT  <=>  no opposite pixel exists.
#define SENT 23742

// Scratch (allocation-free rule: __device__ global). Fully rewritten by
// kernel A on every replay before kernel B reads it -> replay-safe.
__device__ float2 g_part[MAXB * BLK_PER_B];

// distance from position w (0..95) to nearest set bit in 96-bit mask
// (lo = bits 0..63, hi = bits 64..95 in its low 32). >=96 if none.
__device__ __forceinline__ int nearest_bit_dist(unsigned long long lo,
                                                unsigned long long hi, int w) {
    int dr;
    if (w < 64) {
        unsigned long long l = (lo >> w) | ((hi << 1) << (63 - w));
        unsigned long long h2 = hi >> w;
        dr = l ? (__ffsll((long long)l) - 1)
               : (h2 ? 64 + (__ffsll((long long)h2) - 1) : 1000);
    } else {
        unsigned long long l = hi >> (w - 64);
        dr = l ? (__ffsll((long long)l) - 1) : 1000;
    }
    const int wp = w + 1;
    unsigned long long mlo = (wp >= 64) ? lo : (lo & ((1ull << wp) - 1ull));
    unsigned long long mhi = (wp <= 64) ? 0ull : (hi & ((1ull << (wp - 64)) - 1ull));
    int dl;
    if (mhi)      dl = w - (127 - __clzll((long long)mhi));
    else if (mlo) dl = w - (63 - __clzll((long long)mlo));
    else          dl = 1000;
    return min(dl, dr);
}

__device__ __forceinline__ unsigned pack_g(int d, int cap) {
    return (d > 95) ? (unsigned)cap : (unsigned)(d * d);
}

// ---------------- Kernel A: per-block dice partials (no global sync) -------
__global__ void __launch_bounds__(NTHR) dice_partial_kernel(
        const float* __restrict__ inp,
        const int*   __restrict__ tgt) {
    const int b    = blockIdx.x / BLK_PER_B;
    const int wc0  = (blockIdx.x % BLK_PER_B) * COLS_PB;
    const int t    = threadIdx.x;          // 0..767
    const int lane = t & 31;
    const int warp = t >> 5;               // 0..23

    const int h  = t >> 3;                 // 0..95 (this thread's row)
    const int wl = (t & 7) * PX_PT;        // 0,2,..,14 (local col pair)
    const int wc = wc0 + wl;

    __shared__ unsigned bitmap[HW / 32];       // 288 words: image as bits
    __shared__ unsigned gcol[H * COLS_PB];     // packed (g0,g1,cls) per pixel
    __shared__ float    wred[2][NTHR / 32];
    __shared__ int      cnt_s[NTHR / 32];
    __shared__ int      n1_s;

    // phase-B operands issued immediately (latency hidden under bitmap build)
    const float p0 = inp[b * HW + h * W + wc];
    const float p1 = inp[b * HW + h * W + wc + 1];

    // ---- build image bitmap: 3 int4 rounds + 8-lane shfl-OR packing -------
    const int4* tb4 = (const int4*)(tgt + b * HW);
    const int sub = 4 * (lane & 7);            // nibble position in word
    int cnt = 0;
#pragma unroll
    for (int i = 0; i < HW / (NTHR * 4); ++i) {        // 3 rounds
        const int4 v = tb4[i * NTHR + t];
        const unsigned nib = (unsigned)(v.x | (v.y << 1) | (v.z << 2) | (v.w << 3));
        cnt += __popc(nib);
        unsigned wrd = nib << sub;
        wrd |= __shfl_xor_sync(0xFFFFFFFFu, wrd, 1);
        wrd |= __shfl_xor_sync(0xFFFFFFFFu, wrd, 2);
        wrd |= __shfl_xor_sync(0xFFFFFFFFu, wrd, 4);
        if ((lane & 7) == 0) bitmap[i * (NTHR / 8) + (t >> 3)] = wrd;
    }
#pragma unroll
    for (int off = 16; off; off >>= 1) cnt += __shfl_down_sync(0xFFFFFFFFu, cnt, off);
    if (lane == 0) cnt_s[warp] = cnt;
    __syncthreads();

    if (warp == 0) {                               // class-1 count (exact)
        int s = (lane < NTHR / 32) ? cnt_s[lane] : 0;
#pragma unroll
        for (int off = 16; off; off >>= 1) s += __shfl_down_sync(0xFFFFFFFFu, s, off);
        if (lane == 0) n1_s = s;
    }

    // ---- row EDT at (h, wc) and (h, wc+1), both classes, shared row mask --
    const unsigned long long lo =
        (unsigned long long)bitmap[h * 3] |
        ((unsigned long long)bitmap[h * 3 + 1] << 32);
    const unsigned long long hi = (unsigned long long)bitmap[h * 3 + 2];
    const unsigned long long nlo = ~lo;
    const unsigned long long nhi = (~hi) & 0xFFFFFFFFull;

    const int c0 = (wc < 64) ? (int)((lo >> wc) & 1ull)
                             : (int)((hi >> (wc - 64)) & 1ull);
    const int c1 = ((wc + 1) < 64) ? (int)((lo >> (wc + 1)) & 1ull)
                                   : (int)((hi >> (wc + 1 - 64)) & 1ull);

    gcol[h * COLS_PB + wl] =
        pack_g(nearest_bit_dist(nlo, nhi, wc), SENT) |
        (pack_g(nearest_bit_dist(lo, hi, wc), SENT) << 15) |
        ((unsigned)c0 << 30);
    gcol[h * COLS_PB + wl + 1] =
        pack_g(nearest_bit_dist(nlo, nhi, wc + 1), SENT) |
        (pack_g(nearest_bit_dist(lo, hi, wc + 1), SENT) << 15) |
        ((unsigned)c1 << 30);
    __syncthreads();

    const int n1 = n1_s;

    // ---- bounded column scans (exact; r>95 impossible -> capped) ----------
    float r1 = 0.0f, r2 = 0.0f;
#pragma unroll
    for (int px = 0; px < PX_PT; ++px) {
        const int col = wl + px;
        const int c   = px ? c1 : c0;
        const int shift = c ? 0 : 15;
        int best = (int)((gcol[h * COLS_PB + col] >> shift) & 0x7FFFu);
        for (int r = 1; r <= 95 && r * r < best; ++r) {
            const int rr = r * r;
            const int up = h - r, dn = h + r;
            if (up >= 0) best = min(best, rr + (int)((gcol[up * COLS_PB + col] >> shift) & 0x7FFFu));
            if (dn < H)  best = min(best, rr + (int)((gcol[dn * COLS_PB + col] >> shift) & 0x7FFFu));
        }
        // weight: 10*exp(-dmin/(2*5^2)); no opposite -> exp(-inf)=0; n1<=1 -> 1
        float wgt;
        if (n1 <= 1)           wgt = 1.0f;
        else if (best >= SENT) wgt = 0.0f;
        else                   wgt = 10.0f * __expf(-sqrtf((float)best) * 0.02f);
        const float p  = px ? p1 : p0;
        const float tt = (float)c;
        r1 += wgt * p * tt;
        r2 += wgt * (p + tt);
    }

#pragma unroll
    for (int off = 16; off; off >>= 1) {
        r1 += __shfl_down_sync(0xFFFFFFFFu, r1, off);
        r2 += __shfl_down_sync(0xFFFFFFFFu, r2, off);
    }
    if (lane == 0) { wred[0][warp] = r1; wred[1][warp] = r2; }
    __syncthreads();

    if (warp == 0) {
        float s1 = (lane < NTHR / 32) ? wred[0][lane] : 0.0f;
        float s2 = (lane < NTHR / 32) ? wred[1][lane] : 0.0f;
#pragma unroll
        for (int off = 16; off; off >>= 1) {
            s1 += __shfl_down_sync(0xFFFFFFFFu, s1, off);
            s2 += __shfl_down_sync(0xFFFFFFFFu, s2, off);
        }
        if (lane == 0)
            g_part[blockIdx.x] = make_float2(s1, s2);
        // no fence, no atomic: the graph edge to the combine kernel orders this
    }
}

// ---------------- Kernel B: one-warp deterministic final combine -----------
__global__ void dice_final_kernel(float* __restrict__ out, int B) {
    const int lane = threadIdx.x;

    // predicated parallel loads: all batches' partials issued at once (MLP)
    float2 v[MAXB];
#pragma unroll
    for (int bb = 0; bb < MAXB; ++bb)
        v[bb] = (bb < B && lane < BLK_PER_B) ? g_part[bb * BLK_PER_B + lane]
                                             : make_float2(0.0f, 0.0f);

    float loss = 0.0f;
#pragma unroll
    for (int bb = 0; bb < MAXB; ++bb) {
        float s1 = v[bb].x, s2 = v[bb].y;
        // sum lanes 0..7 (6 active) via 8-wide xor tree; lanes 8..31 are zero
        s1 += __shfl_xor_sync(0xFFFFFFFFu, s1, 4);
        s2 += __shfl_xor_sync(0xFFFFFFFFu, s2, 4);
        s1 += __shfl_xor_sync(0xFFFFFFFFu, s1, 2);
        s2 += __shfl_xor_sync(0xFFFFFFFFu, s2, 2);
        s1 += __shfl_xor_sync(0xFFFFFFFFu, s1, 1);
        s2 += __shfl_xor_sync(0xFFFFFFFFu, s2, 1);
        if (bb < B)
            loss += 1.0f - (2.0f * s1 + 1.0f) / (s2 + 1.0f);
    }
    if (lane == 0) out[0] = loss;
}

extern "C" void kernel_launch(void* const* d_in, const int* in_sizes, int n_in,
                              void* d_out, int out_size) {
    const float* inp = (const float*)d_in[0];   // inputs  [B,1,96,96] float32
    const int*   tgt = (const int*)  d_in[1];   // targets [B,1,96,96] int32
    const int B = in_sizes[1] / HW;

    dice_partial_kernel<<<B * BLK_PER_B, NTHR>>>(inp, tgt);
    dice_final_kernel<<<1, 32>>>((float*)d_out, B);
}